// round 8
// baseline (speedup 1.0000x reference)
#include <cuda_runtime.h>
#include <cuda_fp16.h>
#include <cstdint>

// ---------------------------------------------------------------------------
// TopKRouter via 2-limb fp16 split + mma.sync m16n8k16 (3-product scheme).
// logits = x @ w^T ; softmax ; top-2 (+renorm) ; aux loss.
// x: [T=16384, D=2048] fp32, w: [E=64, D=2048] fp32.
// out (fp32, 4T+1): [indices(2T) | weights(2T) | aux_loss]
// R8 == R7 resubmitted (prior bench was an infra failure, no signal):
// KC 32 -> 64 (half the sync/boundary events; LDG latency fully hidden
// under the 2x compute phase). Everything else identical to R6.
// ---------------------------------------------------------------------------

#define DIM     2048
#define NEXP    64
#define CTAM    128           // tokens per CTA = 8 x m16
#define KC      64            // K per chunk
#define NCHUNK  (DIM / KC)    // 32
#define THREADS 256           // 8 warps, 4x2 warp grid (M32 x N32 per warp)
#define MAXCTA  1024

#define PADH    72            // halves per smem row (144 B = 9*16B, conflict-free)
#define ROWB    (PADH * 2)    // 144
// per buffer: A0,A1 (128*144=18432 B each), B0,B1 (64*144=9216 B each)
#define SA_OFF(buf, l)  ((buf) * 55296 + (l) * 18432)
#define SB_OFF(buf, l)  ((buf) * 55296 + 36864 + (l) * 9216)
#define SMEM_BYTES      110592

__device__ float g_P[MAXCTA * NEXP];
__device__ int   g_cnt[MAXCTA * NEXP];
__device__ float g_lse2[MAXCTA];
__device__ int   g_ctr;      // zero-init; self-resetting each launch

__device__ __forceinline__ uint32_t smem_u32(const void* p) {
    uint32_t a;
    asm("{ .reg .u64 t; cvta.to.shared.u64 t, %1; cvt.u32.u64 %0, t; }" : "=r"(a) : "l"(p));
    return a;
}
__device__ __forceinline__ void ldsm4(uint32_t* r, uint32_t a) {
    asm volatile("ldmatrix.sync.aligned.m8n8.x4.shared.b16 {%0,%1,%2,%3}, [%4];"
                 : "=r"(r[0]), "=r"(r[1]), "=r"(r[2]), "=r"(r[3]) : "r"(a));
}
__device__ __forceinline__ void mma16816(float* c, const uint32_t* a, uint32_t b0, uint32_t b1) {
    asm volatile("mma.sync.aligned.m16n8k16.row.col.f32.f16.f16.f32 "
                 "{%0,%1,%2,%3},{%4,%5,%6,%7},{%8,%9},{%0,%1,%2,%3};"
                 : "+f"(c[0]), "+f"(c[1]), "+f"(c[2]), "+f"(c[3])
                 : "r"(a[0]), "r"(a[1]), "r"(a[2]), "r"(a[3]), "r"(b0), "r"(b1));
}
// round-nearest 2-limb fp16 split of a float pair -> packed half2 limbs
__device__ __forceinline__ void split2(float f0, float f1, uint32_t& l0, uint32_t& l1) {
    __half2 h0 = __floats2half2_rn(f0, f1);
    float2 g = __half22float2(h0);
    __half2 h1 = __floats2half2_rn(f0 - g.x, f1 - g.y);
    l0 = *(uint32_t*)&h0;
    l1 = *(uint32_t*)&h1;
}

__global__ __launch_bounds__(THREADS, 1)
void router_kernel(const float* __restrict__ x, const float* __restrict__ wgl,
                   float* __restrict__ out, int tokens) {
    extern __shared__ char smem[];
    const uint32_t sb = smem_u32(smem);
    const int tid = threadIdx.x, w = tid >> 5, lane = tid & 31;
    const int cta = blockIdx.x, tok0 = cta * CTAM;
    const int mi = w >> 1, ni = w & 1;     // 4x2 warp grid: M32 x N32 per warp

    __shared__ float sm_m[CTAM];
    __shared__ float sm_is[CTAM];
    __shared__ int   cnt_s[NEXP];
    __shared__ float red_s[4];
    __shared__ int   isLast;

    // ---- GEMM mainloop (double-buffered, 1 sync/chunk) ----
    const float4* xg = (const float4*)(x + (size_t)tok0 * DIM);
    // x staging: 8 float4/thread; row = tid/2 (128 rows), col base = (tid&1)*8
    const int rowx = tid >> 1, c4base = (tid & 1) * 8;
    float4 xv[8];
#pragma unroll
    for (int i = 0; i < 8; i++)
        xv[i] = xg[(size_t)rowx * (DIM / 4) + c4base + i];
    // w staging: 4 float4/thread: expert = tid/4, float4 base = (tid&3)*4
    const int er = tid >> 2, kg4 = (tid & 3) * 4;
    float4 wf[4];
#pragma unroll
    for (int i = 0; i < 4; i++)
        wf[i] = ((const float4*)wgl)[(size_t)er * (DIM / 4) + kg4 + i];

    float acc[2][4][4];                     // [m-tile][n8][frag]
#pragma unroll
    for (int t = 0; t < 2; t++)
#pragma unroll
        for (int nb = 0; nb < 4; nb++)
#pragma unroll
            for (int j = 0; j < 4; j++) acc[t][nb][j] = 0.f;

    // ldmatrix lane address components (byte offsets within a tile)
    const uint32_t aOff = (uint32_t)(mi * 32 + (lane & 15)) * ROWB + (lane >> 4) * 16;
    const uint32_t bOff = (uint32_t)(ni * 32 + (lane & 7) + ((lane >> 4) & 1) * 8) * ROWB
                        + ((lane >> 3) & 1) * 16;

    for (int c = 0; c < NCHUNK; c++) {
        const int buf = c & 1;
        // store x limbs (row rowx, cols c4base..c4base+7 float4s)
#pragma unroll
        for (int i = 0; i < 8; i++) {
            uint32_t p0, p1, q0, q1;
            split2(xv[i].x, xv[i].y, p0, q0);
            split2(xv[i].z, xv[i].w, p1, q1);
            uint32_t off = (uint32_t)rowx * ROWB + (c4base + i) * 8;
            *(uint2*)(smem + SA_OFF(buf, 0) + off) = make_uint2(p0, p1);
            *(uint2*)(smem + SA_OFF(buf, 1) + off) = make_uint2(q0, q1);
        }
        // split + store w limbs (8 bytes of halves per float4)
#pragma unroll
        for (int i = 0; i < 4; i++) {
            uint32_t p0, p1, q0, q1;
            split2(wf[i].x, wf[i].y, p0, q0);
            split2(wf[i].z, wf[i].w, p1, q1);
            uint32_t off = (uint32_t)er * ROWB + (kg4 + i) * 8;
            *(uint2*)(smem + SB_OFF(buf, 0) + off) = make_uint2(p0, p1);
            *(uint2*)(smem + SB_OFF(buf, 1) + off) = make_uint2(q0, q1);
        }
        __syncthreads();
        // prefetch next chunk (lands during the ~1536-cycle compute phase)
        if (c + 1 < NCHUNK) {
            int k4 = (c + 1) * (KC / 4);
#pragma unroll
            for (int i = 0; i < 8; i++)
                xv[i] = xg[(size_t)rowx * (DIM / 4) + k4 + c4base + i];
#pragma unroll
            for (int i = 0; i < 4; i++)
                wf[i] = ((const float4*)wgl)[(size_t)er * (DIM / 4) + k4 + kg4 + i];
        }
        // compute: 3 limb products (00, 10, 01); 11 dropped (~6e-9 rel)
        const uint32_t a0b = sb + SA_OFF(buf, 0) + aOff;
        const uint32_t a1b = sb + SA_OFF(buf, 1) + aOff;
        const uint32_t b0b = sb + SB_OFF(buf, 0) + bOff;
        const uint32_t b1b = sb + SB_OFF(buf, 1) + bOff;
#pragma unroll
        for (int ks = 0; ks < 4; ks++) {
            uint32_t af0[2][4], af1[2][4];
#pragma unroll
            for (int t = 0; t < 2; t++) {
                ldsm4(af0[t], a0b + t * 16 * ROWB + ks * 32);
                ldsm4(af1[t], a1b + t * 16 * ROWB + ks * 32);
            }
#pragma unroll
            for (int nb2 = 0; nb2 < 2; nb2++) {
                uint32_t bf[4];
                ldsm4(bf, b0b + nb2 * 16 * ROWB + ks * 32);   // b limb0
#pragma unroll
                for (int t = 0; t < 2; t++) {
                    mma16816(acc[t][nb2 * 2    ], af0[t], bf[0], bf[1]);
                    mma16816(acc[t][nb2 * 2    ], af1[t], bf[0], bf[1]);
                    mma16816(acc[t][nb2 * 2 + 1], af0[t], bf[2], bf[3]);
                    mma16816(acc[t][nb2 * 2 + 1], af1[t], bf[2], bf[3]);
                }
                ldsm4(bf, b1b + nb2 * 16 * ROWB + ks * 32);   // b limb1
#pragma unroll
                for (int t = 0; t < 2; t++) {
                    mma16816(acc[t][nb2 * 2    ], af0[t], bf[0], bf[1]);
                    mma16816(acc[t][nb2 * 2 + 1], af0[t], bf[2], bf[3]);
                }
            }
        }
    }
    __syncthreads();   // smem free for logits overlay

    // ---- epilogue: accumulators -> smem logits [128][66] ----
    float* L = (float*)smem;
    {
        int cb = ni * 32 + (lane & 3) * 2;
#pragma unroll
        for (int t = 0; t < 2; t++) {
            int r0 = mi * 32 + t * 16 + (lane >> 2);
#pragma unroll
            for (int nb = 0; nb < 4; nb++) {
                *(float2*)&L[r0 * 66 + cb + nb * 8]       = make_float2(acc[t][nb][0], acc[t][nb][1]);
                *(float2*)&L[(r0 + 8) * 66 + cb + nb * 8] = make_float2(acc[t][nb][2], acc[t][nb][3]);
            }
        }
    }
    if (tid < NEXP) cnt_s[tid] = 0;
    __syncthreads();

    // ---- pass A: per-token top-2, softmax stats, outputs, z ----
    if (tid < CTAM) {
        const int t = tid;
        const float* Lr = &L[t * 66];
        float v1 = -3.402823466e38f, v2 = -3.402823466e38f;
        int i1 = 0, i2 = 0;
#pragma unroll 8
        for (int e = 0; e < NEXP; e++) {
            float l = Lr[e];
            if (l > v1) { v2 = v1; i2 = i1; v1 = l; i1 = e; }
            else if (l > v2) { v2 = l; i2 = e; }
        }
        float S = 0.f;
#pragma unroll 8
        for (int e = 0; e < NEXP; e++) S += __expf(Lr[e] - v1);
        float invS = 1.f / S;
        sm_m[t] = v1; sm_is[t] = invS;

        float lse = v1 + __logf(S);
        float z2 = lse * lse;
#pragma unroll
        for (int o = 16; o > 0; o >>= 1) z2 += __shfl_down_sync(0xffffffffu, z2, o);
        if (lane == 0) red_s[t >> 5] = z2;

        float e2 = __expf(v2 - v1);
        float inv = 1.f / (1.f + e2);
        int gt = tok0 + t;
        out[gt * 2    ] = (float)i1;
        out[gt * 2 + 1] = (float)i2;
        float* wout = out + 2 * tokens;
        wout[gt * 2    ] = inv;
        wout[gt * 2 + 1] = e2 * inv;
        atomicAdd(&cnt_s[i1], 1);
        atomicAdd(&cnt_s[i2], 1);
    }
    __syncthreads();

    // ---- pass B: per-expert softmax-weight partials (fixed order) ----
    if (tid < NEXP) {
        const int e = tid;
        float P = 0.f;
#pragma unroll 8
        for (int t = 0; t < CTAM; t++)
            P += __expf(L[t * 66 + e] - sm_m[t]) * sm_is[t];
        g_P[cta * NEXP + e]   = P;
        g_cnt[cta * NEXP + e] = cnt_s[e];
    }
    if (tid == 0) g_lse2[cta] = ((red_s[0] + red_s[1]) + red_s[2]) + red_s[3];

    // ---- last CTA finalizes (deterministic fixed-order reduction) ----
    __threadfence();
    __syncthreads();
    if (tid == 0) {
        int prev = atomicAdd(&g_ctr, 1);
        isLast = (prev == (int)gridDim.x - 1);
    }
    __syncthreads();
    if (!isLast) return;

    {
        const int nCta = (int)gridDim.x;
        __shared__ float sP2[2][NEXP];
        __shared__ float sC2[2][NEXP];
        __shared__ float sZ2[MAXCTA / 4];
        if (tid < 128) {
            int s = tid >> 6, e = tid & 63;
            float P = 0.f, C = 0.f;
            for (int c2 = s; c2 < nCta; c2 += 2) {    // fixed per-slice order
                P += g_P[c2 * NEXP + e];
                C += (float)g_cnt[c2 * NEXP + e];
            }
            sP2[s][e] = P; sC2[s][e] = C;
        }
        if (tid < 256) sZ2[tid] = (tid < nCta) ? g_lse2[tid] : 0.f;
        __syncthreads();
        if (tid == 0) {
            float tsum = 0.f;
            for (int e = 0; e < NEXP; e++) {
                float P = sP2[0][e] + sP2[1][e];
                float C = sC2[0][e] + sC2[1][e];
                tsum += (C / (float)(tokens * 2)) * (P / (float)tokens);
            }
            float z = 0.f;
            for (int i = 0; i < 256; i++) z += sZ2[i];
            out[4 * tokens] = 0.01f * ((float)NEXP * tsum) + 0.001f * (z / (float)tokens);
            g_ctr = 0;   // self-reset for next launch / graph replay
        }
    }
}

extern "C" void kernel_launch(void* const* d_in, const int* in_sizes, int n_in,
                              void* d_out, int out_size) {
    const float* x = (const float*)d_in[0];
    const float* w = (const float*)d_in[1];
    float* out = (float*)d_out;
    int tokens = in_sizes[0] / DIM;              // 16384
    int nCta   = tokens / CTAM;                  // 128 (exact)
    cudaFuncSetAttribute(router_kernel, cudaFuncAttributeMaxDynamicSharedMemorySize, SMEM_BYTES);
    router_kernel<<<nCta, THREADS, SMEM_BYTES>>>(x, w, out, tokens);
}

// round 9
// speedup vs baseline: 1.2286x; 1.2286x over previous
#include <cuda_runtime.h>
#include <cuda_fp16.h>
#include <cstdint>

// ---------------------------------------------------------------------------
// TopKRouter via 2-limb fp16 split + mma.sync m16n8k16 (3-product scheme).
// logits = x @ w^T ; softmax ; top-2 (+renorm) ; aux loss.
// x: [T=16384, D=2048] fp32, w: [E=64, D=2048] fp32.
// out (fp32, 4T+1): [indices(2T) | weights(2T) | aux_loss]
// R9: KC back to 32 (R8's KC=64 regressed: reg pressure). 512 threads,
//     4x4 warp grid, warp tile M32xN16 -> 4 warps/SMSP for latency hiding.
// ---------------------------------------------------------------------------

#define DIM     2048
#define NEXP    64
#define CTAM    128           // tokens per CTA = 8 x m16
#define KC      32            // K per chunk
#define NCHUNK  (DIM / KC)    // 64
#define THREADS 512           // 16 warps, 4x4 warp grid (M32 x N16 per warp)
#define MAXCTA  1024

#define PADH    40            // halves per smem row (80 B) -> conflict-free ldmatrix
#define ROWB    (PADH * 2)    // 80
// per buffer: A0,A1 (128*80=10240 B each), B0,B1 (64*80=5120 B each)
#define SA_OFF(buf, l)  ((buf) * 30720 + (l) * 10240)
#define SB_OFF(buf, l)  ((buf) * 30720 + 20480 + (l) * 5120)
#define SMEM_BYTES      61440

__device__ float g_P[MAXCTA * NEXP];
__device__ int   g_cnt[MAXCTA * NEXP];
__device__ float g_lse2[MAXCTA];
__device__ int   g_ctr;      // zero-init; self-resetting each launch

__device__ __forceinline__ uint32_t smem_u32(const void* p) {
    uint32_t a;
    asm("{ .reg .u64 t; cvta.to.shared.u64 t, %1; cvt.u32.u64 %0, t; }" : "=r"(a) : "l"(p));
    return a;
}
__device__ __forceinline__ void ldsm4(uint32_t* r, uint32_t a) {
    asm volatile("ldmatrix.sync.aligned.m8n8.x4.shared.b16 {%0,%1,%2,%3}, [%4];"
                 : "=r"(r[0]), "=r"(r[1]), "=r"(r[2]), "=r"(r[3]) : "r"(a));
}
__device__ __forceinline__ void mma16816(float* c, const uint32_t* a, uint32_t b0, uint32_t b1) {
    asm volatile("mma.sync.aligned.m16n8k16.row.col.f32.f16.f16.f32 "
                 "{%0,%1,%2,%3},{%4,%5,%6,%7},{%8,%9},{%0,%1,%2,%3};"
                 : "+f"(c[0]), "+f"(c[1]), "+f"(c[2]), "+f"(c[3])
                 : "r"(a[0]), "r"(a[1]), "r"(a[2]), "r"(a[3]), "r"(b0), "r"(b1));
}
// round-nearest 2-limb fp16 split of a float pair -> packed half2 limbs
__device__ __forceinline__ void split2(float f0, float f1, uint32_t& l0, uint32_t& l1) {
    __half2 h0 = __floats2half2_rn(f0, f1);
    float2 g = __half22float2(h0);
    __half2 h1 = __floats2half2_rn(f0 - g.x, f1 - g.y);
    l0 = *(uint32_t*)&h0;
    l1 = *(uint32_t*)&h1;
}

__global__ __launch_bounds__(THREADS, 1)
void router_kernel(const float* __restrict__ x, const float* __restrict__ wgl,
                   float* __restrict__ out, int tokens) {
    extern __shared__ char smem[];
    const uint32_t sb = smem_u32(smem);
    const int tid = threadIdx.x, w = tid >> 5, lane = tid & 31;
    const int cta = blockIdx.x, tok0 = cta * CTAM;
    const int mi = w >> 2, ni = w & 3;     // 4x4 warp grid: M32 x N16 per warp

    __shared__ float sm_m[CTAM];
    __shared__ float sm_is[CTAM];
    __shared__ int   cnt_s[NEXP];
    __shared__ float red_s[4];
    __shared__ int   isLast;

    // ---- GEMM mainloop (double-buffered, 1 sync/chunk) ----
    const float4* xg = (const float4*)(x + (size_t)tok0 * DIM);
    // x staging: 2 float4/thread; idx = i*512+tid: row = idx/8 (128), c4 = idx%8
    int rowx[2], c4x[2];
    float4 xv[2];
#pragma unroll
    for (int i = 0; i < 2; i++) {
        int idx = i * THREADS + tid;
        rowx[i] = idx >> 3; c4x[i] = idx & 7;
        xv[i] = xg[(size_t)rowx[i] * (DIM / 4) + c4x[i]];
    }
    // w staging: 1 float4/thread: expert = tid/8, float4 col = tid&7
    const int er = tid >> 3, kg4 = tid & 7;
    float4 wf = ((const float4*)wgl)[(size_t)er * (DIM / 4) + kg4];

    float acc[2][2][4];                     // [m-tile][n8][frag]
#pragma unroll
    for (int t = 0; t < 2; t++)
#pragma unroll
        for (int nb = 0; nb < 2; nb++)
#pragma unroll
            for (int j = 0; j < 4; j++) acc[t][nb][j] = 0.f;

    // ldmatrix lane address components (byte offsets within a tile)
    const uint32_t aOff = (uint32_t)(mi * 32 + (lane & 15)) * ROWB + (lane >> 4) * 16;
    const uint32_t bOff = (uint32_t)(ni * 16 + (lane & 7) + ((lane >> 4) & 1) * 8) * ROWB
                        + ((lane >> 3) & 1) * 16;

    for (int c = 0; c < NCHUNK; c++) {
        const int buf = c & 1;
        // store x limbs
#pragma unroll
        for (int i = 0; i < 2; i++) {
            uint32_t p0, p1, q0, q1;
            split2(xv[i].x, xv[i].y, p0, q0);
            split2(xv[i].z, xv[i].w, p1, q1);
            uint32_t off = (uint32_t)rowx[i] * ROWB + c4x[i] * 8;
            *(uint2*)(smem + SA_OFF(buf, 0) + off) = make_uint2(p0, p1);
            *(uint2*)(smem + SA_OFF(buf, 1) + off) = make_uint2(q0, q1);
        }
        // split + store w limbs (8 bytes of halves per float4)
        {
            uint32_t p0, p1, q0, q1;
            split2(wf.x, wf.y, p0, q0);
            split2(wf.z, wf.w, p1, q1);
            uint32_t off = (uint32_t)er * ROWB + kg4 * 8;
            *(uint2*)(smem + SB_OFF(buf, 0) + off) = make_uint2(p0, p1);
            *(uint2*)(smem + SB_OFF(buf, 1) + off) = make_uint2(q0, q1);
        }
        __syncthreads();
        // prefetch next chunk
        if (c + 1 < NCHUNK) {
            int k4 = (c + 1) * (KC / 4);
#pragma unroll
            for (int i = 0; i < 2; i++)
                xv[i] = xg[(size_t)rowx[i] * (DIM / 4) + k4 + c4x[i]];
            wf = ((const float4*)wgl)[(size_t)er * (DIM / 4) + k4 + kg4];
        }
        // compute: 3 limb products (00, 10, 01); 11 dropped (~6e-9 rel)
        const uint32_t a0b = sb + SA_OFF(buf, 0) + aOff;
        const uint32_t a1b = sb + SA_OFF(buf, 1) + aOff;
        const uint32_t b0b = sb + SB_OFF(buf, 0) + bOff;
        const uint32_t b1b = sb + SB_OFF(buf, 1) + bOff;
#pragma unroll
        for (int ks = 0; ks < 2; ks++) {
            uint32_t af0[2][4], af1[2][4], bf[4];
#pragma unroll
            for (int t = 0; t < 2; t++) {
                ldsm4(af0[t], a0b + t * 16 * ROWB + ks * 32);
                ldsm4(af1[t], a1b + t * 16 * ROWB + ks * 32);
            }
            ldsm4(bf, b0b + ks * 32);                     // b limb0 (n16 x k16)
#pragma unroll
            for (int t = 0; t < 2; t++) {
                mma16816(acc[t][0], af0[t], bf[0], bf[1]);
                mma16816(acc[t][0], af1[t], bf[0], bf[1]);
                mma16816(acc[t][1], af0[t], bf[2], bf[3]);
                mma16816(acc[t][1], af1[t], bf[2], bf[3]);
            }
            ldsm4(bf, b1b + ks * 32);                     // b limb1
#pragma unroll
            for (int t = 0; t < 2; t++) {
                mma16816(acc[t][0], af0[t], bf[0], bf[1]);
                mma16816(acc[t][1], af0[t], bf[2], bf[3]);
            }
        }
    }
    __syncthreads();   // smem free for logits overlay

    // ---- epilogue: accumulators -> smem logits [128][66] ----
    float* L = (float*)smem;
    {
        int cb = ni * 16 + (lane & 3) * 2;
#pragma unroll
        for (int t = 0; t < 2; t++) {
            int r0 = mi * 32 + t * 16 + (lane >> 2);
#pragma unroll
            for (int nb = 0; nb < 2; nb++) {
                *(float2*)&L[r0 * 66 + cb + nb * 8]       = make_float2(acc[t][nb][0], acc[t][nb][1]);
                *(float2*)&L[(r0 + 8) * 66 + cb + nb * 8] = make_float2(acc[t][nb][2], acc[t][nb][3]);
            }
        }
    }
    if (tid < NEXP) cnt_s[tid] = 0;
    __syncthreads();

    // ---- pass A: per-token top-2, softmax stats, outputs, z ----
    if (tid < CTAM) {
        const int t = tid;
        const float* Lr = &L[t * 66];
        float v1 = -3.402823466e38f, v2 = -3.402823466e38f;
        int i1 = 0, i2 = 0;
#pragma unroll 8
        for (int e = 0; e < NEXP; e++) {
            float l = Lr[e];
            if (l > v1) { v2 = v1; i2 = i1; v1 = l; i1 = e; }
            else if (l > v2) { v2 = l; i2 = e; }
        }
        float S = 0.f;
#pragma unroll 8
        for (int e = 0; e < NEXP; e++) S += __expf(Lr[e] - v1);
        float invS = 1.f / S;
        sm_m[t] = v1; sm_is[t] = invS;

        float lse = v1 + __logf(S);
        float z2 = lse * lse;
#pragma unroll
        for (int o = 16; o > 0; o >>= 1) z2 += __shfl_down_sync(0xffffffffu, z2, o);
        if (lane == 0) red_s[t >> 5] = z2;

        float e2 = __expf(v2 - v1);
        float inv = 1.f / (1.f + e2);
        int gt = tok0 + t;
        out[gt * 2    ] = (float)i1;
        out[gt * 2 + 1] = (float)i2;
        float* wout = out + 2 * tokens;
        wout[gt * 2    ] = inv;
        wout[gt * 2 + 1] = e2 * inv;
        atomicAdd(&cnt_s[i1], 1);
        atomicAdd(&cnt_s[i2], 1);
    }
    __syncthreads();

    // ---- pass B: per-expert softmax-weight partials (fixed order) ----
    if (tid < NEXP) {
        const int e = tid;
        float P = 0.f;
#pragma unroll 8
        for (int t = 0; t < CTAM; t++)
            P += __expf(L[t * 66 + e] - sm_m[t]) * sm_is[t];
        g_P[cta * NEXP + e]   = P;
        g_cnt[cta * NEXP + e] = cnt_s[e];
    }
    if (tid == 0) g_lse2[cta] = ((red_s[0] + red_s[1]) + red_s[2]) + red_s[3];

    // ---- last CTA finalizes (deterministic fixed-order reduction) ----
    __threadfence();
    __syncthreads();
    if (tid == 0) {
        int prev = atomicAdd(&g_ctr, 1);
        isLast = (prev == (int)gridDim.x - 1);
    }
    __syncthreads();
    if (!isLast) return;

    {
        const int nCta = (int)gridDim.x;
        __shared__ float sP2[2][NEXP];
        __shared__ float sC2[2][NEXP];
        __shared__ float sZ2[MAXCTA / 4];
        if (tid < 128) {
            int s = tid >> 6, e = tid & 63;
            float P = 0.f, C = 0.f;
            for (int c2 = s; c2 < nCta; c2 += 2) {    // fixed per-slice order
                P += g_P[c2 * NEXP + e];
                C += (float)g_cnt[c2 * NEXP + e];
            }
            sP2[s][e] = P; sC2[s][e] = C;
        }
        if (tid < 256) sZ2[tid] = (tid < nCta) ? g_lse2[tid] : 0.f;
        __syncthreads();
        if (tid == 0) {
            float tsum = 0.f;
            for (int e = 0; e < NEXP; e++) {
                float P = sP2[0][e] + sP2[1][e];
                float C = sC2[0][e] + sC2[1][e];
                tsum += (C / (float)(tokens * 2)) * (P / (float)tokens);
            }
            float z = 0.f;
            for (int i = 0; i < 256; i++) z += sZ2[i];
            out[4 * tokens] = 0.01f * ((float)NEXP * tsum) + 0.001f * (z / (float)tokens);
            g_ctr = 0;   // self-reset for next launch / graph replay
        }
    }
}

extern "C" void kernel_launch(void* const* d_in, const int* in_sizes, int n_in,
                              void* d_out, int out_size) {
    const float* x = (const float*)d_in[0];
    const float* w = (const float*)d_in[1];
    float* out = (float*)d_out;
    int tokens = in_sizes[0] / DIM;              // 16384
    int nCta   = tokens / CTAM;                  // 128 (exact)
    cudaFuncSetAttribute(router_kernel, cudaFuncAttributeMaxDynamicSharedMemorySize, SMEM_BYTES);
    router_kernel<<<nCta, THREADS, SMEM_BYTES>>>(x, w, out, tokens);
}